// round 14
// baseline (speedup 1.0000x reference)
#include <cuda_runtime.h>
#include <cuda_bf16.h>
#include <cstdint>
#include <cstring>

typedef unsigned long long ull;

#define B_DIM    128
#define IN_DIM   1024
#define OUT_DIM  1024
#define KSPLIT   16
#define K_TILE   64
#define N_TILE   64
#define THREADS  256
#define GRID     (KSPLIT * (OUT_DIM / N_TILE))   // 256 CTAs, 2/SM, one wave

#define K_PAD    72                               // bf16 elems/row
#define ROW_B    (K_PAD * 2)                      // 144B: 16B-aligned, rotates banks
#define XS_HI    0
#define XS_LO    (B_DIM * ROW_B)                  // 18432
#define WS_HI    (2 * B_DIM * ROW_B)              // 36864
#define WS_LO    (WS_HI + N_TILE * ROW_B)         // 46080
#define S_MHL    (WS_LO + N_TILE * ROW_B)         // 55296
#define SMEM_BYTES (S_MHL + N_TILE * 16 * 4)      // 59392 (~58 KB -> 2 CTAs/SM)

// partials (8 MB) + per-o-tile counters (monotonic = replay-safe)
__device__ float g_part[KSPLIT * B_DIM * OUT_DIM];
__device__ unsigned g_done[OUT_DIM / N_TILE];

__device__ __forceinline__ uint32_t smem_u32(const void* p) {
    uint32_t a;
    asm("{ .reg .u64 t; cvta.to.shared.u64 t, %1; cvt.u32.u64 %0, t; }"
        : "=r"(a) : "l"(p));
    return a;
}
__device__ __forceinline__ uint32_t bf2u(__nv_bfloat162 v) {
    uint32_t u; memcpy(&u, &v, 4); return u;
}
__device__ __forceinline__ unsigned short bfbits(__nv_bfloat16 v) {
    unsigned short u; memcpy(&u, &v, 2); return u;
}

#define LDSM_X4(r0, r1, r2, r3, addr)                                       \
    asm volatile("ldmatrix.sync.aligned.m8n8.x4.shared.b16 {%0,%1,%2,%3}, [%4];" \
                 : "=r"(r0), "=r"(r1), "=r"(r2), "=r"(r3) : "r"(addr))

#define MMA_BF16(c, a0, a1, a2, a3, b0, b1)                                 \
    asm volatile("mma.sync.aligned.m16n8k16.row.col.f32.bf16.bf16.f32 "     \
                 "{%0,%1,%2,%3}, {%4,%5,%6,%7}, {%8,%9}, {%0,%1,%2,%3};"    \
                 : "+f"((c)[0]), "+f"((c)[1]), "+f"((c)[2]), "+f"((c)[3])   \
                 : "r"(a0), "r"(a1), "r"(a2), "r"(a3), "r"(b0), "r"(b1))

// ---------------------------------------------------------------------------
// 2-CTA/SM fused kernel. Per CTA: 128 batches x 64 outputs x 64 K.
// 8 warps, warp = 16 batches x 64 outputs (R7-proven fragment addressing).
// Phases overlap ACROSS the two co-resident CTAs.
// ---------------------------------------------------------------------------
__global__ void __launch_bounds__(THREADS, 2)
sic_mma(const float* __restrict__ x, const float* __restrict__ means,
        const float* __restrict__ bias, const int* __restrict__ dest,
        float* __restrict__ out)
{
    extern __shared__ __align__(16) char smem[];
    const uint32_t sb = smem_u32(smem);
    uint32_t* mhl = reinterpret_cast<uint32_t*>(smem + S_MHL);
    const int tid = threadIdx.x;
    const int wid = tid >> 5, lid = tid & 31;
    const int ks  = blockIdx.x & (KSPLIT - 1);
    const int oy  = blockIdx.x >> 4;
    const int o0  = oy * N_TILE;
    const int k0  = ks * K_TILE;

    // ---- 1. dest loads FIRST: 64 rows x 16 int4 = 1024 int4 ----
    int4 dd[4];
#pragma unroll
    for (int j = 0; j < 4; j++) {
        const int s = tid + j * THREADS;     // 0..1023
        const int o = s >> 4;
        const int kq = s & 15;
        dd[j] = reinterpret_cast<const int4*>(dest)
                    [(size_t)(o0 + o) * (IN_DIM / 4) + (k0 >> 2) + kq];
    }

    // ---- 2. means slice -> packed hi|lo smem table (1024 entries) ----
#pragma unroll
    for (int j = 0; j < 4; j++) {
        const int i = tid + j * THREADS;     // 0..1023
        const float m = means[o0 * 16 + i];
        const __nv_bfloat16 h = __float2bfloat16(m);
        const __nv_bfloat16 l = __float2bfloat16(m - __bfloat162float(h));
        mhl[i] = (uint32_t)bfbits(h) | ((uint32_t)bfbits(l) << 16);
    }

    // ---- 3. x slice [128 x 64] -> bf16 hi/lo planes ----
    for (int idx = tid; idx < B_DIM * (K_TILE / 4); idx += THREADS) {
        const int row = idx >> 4;
        const int k   = (idx & 15) << 2;
        const float4 v = *reinterpret_cast<const float4*>(x + (size_t)row * IN_DIM + k0 + k);
        const __nv_bfloat16 hx = __float2bfloat16(v.x), hy = __float2bfloat16(v.y);
        const __nv_bfloat16 hz = __float2bfloat16(v.z), hw = __float2bfloat16(v.w);
        uint2 hi, lo;
        hi.x = bf2u(__nv_bfloat162(hx, hy));
        hi.y = bf2u(__nv_bfloat162(hz, hw));
        lo.x = bf2u(__floats2bfloat162_rn(v.x - __bfloat162float(hx),
                                          v.y - __bfloat162float(hy)));
        lo.y = bf2u(__floats2bfloat162_rn(v.z - __bfloat162float(hz),
                                          v.w - __bfloat162float(hw)));
        const uint32_t byte = (uint32_t)row * ROW_B + k * 2;
        *reinterpret_cast<uint2*>(smem + XS_HI + byte) = hi;
        *reinterpret_cast<uint2*>(smem + XS_LO + byte) = lo;
    }
    __syncthreads();   // means table ready

    // ---- 4. W gather: LDS table + PRMT split ----
    {
        const int tbase = o0 * 16;
        uint32_t m[4][4];
#pragma unroll
        for (int j = 0; j < 4; j++) {
            m[j][0] = mhl[dd[j].x - tbase]; m[j][1] = mhl[dd[j].y - tbase];
            m[j][2] = mhl[dd[j].z - tbase]; m[j][3] = mhl[dd[j].w - tbase];
        }
#pragma unroll
        for (int j = 0; j < 4; j++) {
            const int s = tid + j * THREADS;
            const int o = s >> 4;
            const int kq = s & 15;
            uint2 hi, lo;
            hi.x = __byte_perm(m[j][0], m[j][1], 0x5410);
            hi.y = __byte_perm(m[j][2], m[j][3], 0x5410);
            lo.x = __byte_perm(m[j][0], m[j][1], 0x7632);
            lo.y = __byte_perm(m[j][2], m[j][3], 0x7632);
            *reinterpret_cast<uint2*>(smem + WS_HI + o * ROW_B + kq * 8) = hi;
            *reinterpret_cast<uint2*>(smem + WS_LO + o * ROW_B + kq * 8) = lo;
        }
    }
    __syncthreads();

    // ---- 5. mma.sync mainloop: warp = 16 batches x 64 outputs, K=64 ----
    const int m0 = wid * 16;
    float acc[8][4];
#pragma unroll
    for (int n = 0; n < 8; n++)
#pragma unroll
        for (int i = 0; i < 4; i++) acc[n][i] = 0.f;

    const uint32_t a_row  = (uint32_t)(m0 + (lid & 15)) * ROW_B;
    const uint32_t a_coff = (uint32_t)(lid >> 4) * 16;
    const uint32_t b_row  = (uint32_t)(lid & 7) * ROW_B;
    const uint32_t b_coff = (uint32_t)(lid >> 3) * 16;

#pragma unroll
    for (int kp = 0; kp < 2; kp++) {                 // k = kp*32
        uint32_t ah0[4], ah1[4], al0[4], al1[4];
        {
            const uint32_t c0 = (uint32_t)(kp * 64) + a_coff;
            const uint32_t c1 = c0 + 32;
            LDSM_X4(ah0[0], ah0[1], ah0[2], ah0[3], sb + XS_HI + a_row + c0);
            LDSM_X4(ah1[0], ah1[1], ah1[2], ah1[3], sb + XS_HI + a_row + c1);
            LDSM_X4(al0[0], al0[1], al0[2], al0[3], sb + XS_LO + a_row + c0);
            LDSM_X4(al1[0], al1[1], al1[2], al1[3], sb + XS_LO + a_row + c1);
        }
#pragma unroll
        for (int n = 0; n < 8; n++) {
            const uint32_t bbase = (uint32_t)(n * 8) * ROW_B
                                 + (uint32_t)(kp * 64) + b_coff;
            uint32_t bh[4], bl[4];
            LDSM_X4(bh[0], bh[1], bh[2], bh[3], sb + WS_HI + b_row + bbase);
            LDSM_X4(bl[0], bl[1], bl[2], bl[3], sb + WS_LO + b_row + bbase);
            MMA_BF16(acc[n], ah0[0], ah0[1], ah0[2], ah0[3], bh[0], bh[1]);
            MMA_BF16(acc[n], al0[0], al0[1], al0[2], al0[3], bh[0], bh[1]);
            MMA_BF16(acc[n], ah0[0], ah0[1], ah0[2], ah0[3], bl[0], bl[1]);
            MMA_BF16(acc[n], ah1[0], ah1[1], ah1[2], ah1[3], bh[2], bh[3]);
            MMA_BF16(acc[n], al1[0], al1[1], al1[2], al1[3], bh[2], bh[3]);
            MMA_BF16(acc[n], ah1[0], ah1[1], ah1[2], ah1[3], bl[2], bl[3]);
        }
    }

    // ---- 6. write partials ----
    {
        const int g  = lid >> 2;
        const int tg = lid & 3;
        float* r0 = g_part + ((size_t)(ks * B_DIM + m0 + g))     * OUT_DIM + o0 + 2 * tg;
        float* r1 = g_part + ((size_t)(ks * B_DIM + m0 + g + 8)) * OUT_DIM + o0 + 2 * tg;
#pragma unroll
        for (int n = 0; n < 8; n++) {
            *reinterpret_cast<float2*>(r0 + n * 8) = make_float2(acc[n][0], acc[n][1]);
            *reinterpret_cast<float2*>(r1 + n * 8) = make_float2(acc[n][2], acc[n][3]);
        }
    }

    // ---- 7. per-tile barrier: all 16 CTAs of this oy (monotonic) ----
    __threadfence();
    __syncthreads();
    if (tid == 0) {
        const unsigned v = atomicAdd(&g_done[oy], 1u) + 1u;
        const unsigned target = ((v - 1u) / (unsigned)KSPLIT + 1u) * (unsigned)KSPLIT;
        while (*(volatile unsigned*)&g_done[oy] < target) { }
    }
    __syncthreads();
    __threadfence();

    // ---- 8. distributed reduce: CTA ks owns batches ks*8..+7 (1 f2/thr) ----
    {
        const int b  = ks * 8 + (tid >> 5);
        const int oo = (tid & 31) * 2;
        const float* p = g_part + (size_t)b * OUT_DIM + o0 + oo;
        float2 a = make_float2(0.f, 0.f);
#pragma unroll
        for (int k = 0; k < KSPLIT; k++) {
            const float2 v = *reinterpret_cast<const float2*>(
                p + (size_t)k * (B_DIM * OUT_DIM));
            a.x += v.x; a.y += v.y;
        }
        const float2 bb = *reinterpret_cast<const float2*>(bias + o0 + oo);
        a.x += bb.x; a.y += bb.y;
        *reinterpret_cast<float2*>(out + (size_t)b * OUT_DIM + o0 + oo) = a;
    }
}

extern "C" void kernel_launch(void* const* d_in, const int* in_sizes, int n_in,
                              void* d_out, int out_size)
{
    (void)in_sizes; (void)n_in; (void)out_size;
    const float* x     = (const float*)d_in[0];   // [128,1024] f32
    const float* means = (const float*)d_in[1];   // [1024,16]  f32
    const float* bias  = (const float*)d_in[2];   // [1024]     f32
    // d_in[3] = col_idx (identity layout per row; unused)
    const int*   dest  = (const int*)d_in[4];     // [1024*1024] i32

    cudaFuncSetAttribute(sic_mma, cudaFuncAttributeMaxDynamicSharedMemorySize,
                         SMEM_BYTES);
    sic_mma<<<GRID, THREADS, SMEM_BYTES>>>(x, means, bias, dest, (float*)d_out);
}

// round 17
// speedup vs baseline: 1.0247x; 1.0247x over previous
#include <cuda_runtime.h>
#include <cuda_bf16.h>
#include <cstdint>
#include <cstring>

typedef unsigned long long ull;

#define B_DIM    128
#define IN_DIM   1024
#define OUT_DIM  1024
#define KSPLIT   8
#define K_TILE   128
#define N_TILE   64
#define THREADS  512
#define GRID     (KSPLIT * (OUT_DIM / N_TILE))   // 128 CTAs, one wave

#define K_PAD    136                              // bf16 elems/row; 272B stride
#define ROW_B    (K_PAD * 2)                      // 272
// smem layout (dynamic, bytes)
#define XS_HI    0
#define XS_LO    34816                            // + 128*272
#define S_DEST   69632                            // raw dest tile, 32 KB
#define S_MHL    102400                           // packed means table, 4 KB
#define S_MRAW   106496                           // raw means slice, 4 KB
#define S_XRAW   110592                           // raw x slice, 64 KB
#define WS_HI    110592                           // overlaps XRAW (dead after convert)
#define WS_LO    (WS_HI + N_TILE * ROW_B)         // 128000
#define SMEM_BYTES (S_XRAW + 65536)               // 176128 (~172 KB, 1 CTA/SM)

// partials (4 MB) + per-o-tile counters (monotonic = replay-safe)
__device__ float g_part[KSPLIT * B_DIM * OUT_DIM];
__device__ unsigned g_done[OUT_DIM / N_TILE];

__device__ __forceinline__ uint32_t smem_u32(const void* p) {
    uint32_t a;
    asm("{ .reg .u64 t; cvta.to.shared.u64 t, %1; cvt.u32.u64 %0, t; }"
        : "=r"(a) : "l"(p));
    return a;
}
__device__ __forceinline__ uint32_t bf2u(__nv_bfloat162 v) {
    uint32_t u; memcpy(&u, &v, 4); return u;
}
__device__ __forceinline__ unsigned short bfbits(__nv_bfloat16 v) {
    unsigned short u; memcpy(&u, &v, 2); return u;
}

#define CP_ASYNC16(sa, gp) \
    asm volatile("cp.async.ca.shared.global [%0], [%1], 16;" :: "r"(sa), "l"(gp))
#define CP_COMMIT()  asm volatile("cp.async.commit_group;" ::: "memory")
#define CP_WAIT(n)   asm volatile("cp.async.wait_group %0;" :: "n"(n) : "memory")

#define LDSM_X4(r0, r1, r2, r3, addr)                                       \
    asm volatile("ldmatrix.sync.aligned.m8n8.x4.shared.b16 {%0,%1,%2,%3}, [%4];" \
                 : "=r"(r0), "=r"(r1), "=r"(r2), "=r"(r3) : "r"(addr))

#define MMA_BF16(c, a0, a1, a2, a3, b0, b1)                                 \
    asm volatile("mma.sync.aligned.m16n8k16.row.col.f32.bf16.bf16.f32 "     \
                 "{%0,%1,%2,%3}, {%4,%5,%6,%7}, {%8,%9}, {%0,%1,%2,%3};"    \
                 : "+f"((c)[0]), "+f"((c)[1]), "+f"((c)[2]), "+f"((c)[3])   \
                 : "r"(a0), "r"(a1), "r"(a2), "r"(a3), "r"(b0), "r"(b1))

// ---------------------------------------------------------------------------
// Single fused kernel (R12 topology, cp.async staging):
//  cp.async {x raw, means raw}=g0, {dest}=g1 -> wait g0 -> BARRIER (cross-
//  thread publish; the R14 bug) -> convert from LDS -> sync -> gather
//  (dest LDS + means table LDS + PRMT) -> mma.sync 3-pass -> partials ->
//  per-tile barrier (8 CTAs) -> distributed reduce + bias.
// ---------------------------------------------------------------------------
__global__ void __launch_bounds__(THREADS, 1)
sic_mma(const float* __restrict__ x, const float* __restrict__ means,
        const float* __restrict__ bias, const int* __restrict__ dest,
        float* __restrict__ out)
{
    extern __shared__ __align__(16) char smem[];
    const uint32_t sb = smem_u32(smem);
    uint32_t* mhl = reinterpret_cast<uint32_t*>(smem + S_MHL);
    const int tid = threadIdx.x;
    const int wid = tid >> 5, lid = tid & 31;
    const int ks  = blockIdx.x & (KSPLIT - 1);
    const int oy  = blockIdx.x >> 3;
    const int o0  = oy * N_TILE;
    const int k0  = ks * K_TILE;

    // ---- 1. cp.async staging: group0 = x raw + means raw; group1 = dest ----
#pragma unroll
    for (int j = 0; j < 8; j++) {                 // x: 4096 16B chunks
        const int c   = tid + j * THREADS;
        const int row = c >> 5;
        const int ci  = c & 31;
        CP_ASYNC16(sb + S_XRAW + c * 16,
                   (const char*)(x + (size_t)row * IN_DIM + k0 + ci * 4));
    }
    if (tid < 256)                                // means: 256 chunks
        CP_ASYNC16(sb + S_MRAW + tid * 16, (const char*)(means + o0 * 16 + tid * 4));
    CP_COMMIT();
#pragma unroll
    for (int j = 0; j < 4; j++) {                 // dest: 2048 16B chunks
        const int c  = tid + j * THREADS;
        const int o  = c >> 5;
        const int kq = c & 31;
        CP_ASYNC16(sb + S_DEST + c * 16,
                   (const char*)(dest + (size_t)(o0 + o) * IN_DIM + k0 + kq * 4));
    }
    CP_COMMIT();

    CP_WAIT(1);        // group0 (x + means) landed (this thread's view)
    __syncthreads();   // FIX: publish group0 data to ALL threads before reads

    // ---- 2. means raw -> packed hi|lo table (LDS reads) ----
#pragma unroll
    for (int j = 0; j < 2; j++) {
        const int i = tid + j * THREADS;          // 0..1023
        const float m = reinterpret_cast<const float*>(smem + S_MRAW)[i];
        const __nv_bfloat16 h = __float2bfloat16(m);
        const __nv_bfloat16 l = __float2bfloat16(m - __bfloat162float(h));
        mhl[i] = (uint32_t)bfbits(h) | ((uint32_t)bfbits(l) << 16);
    }

    // ---- 3. x raw -> bf16 hi/lo planes (LDS reads, 29cyc not 234) ----
#pragma unroll
    for (int j = 0; j < 8; j++) {
        const int c   = tid + j * THREADS;        // 0..4095
        const int row = c >> 5;
        const int k   = (c & 31) << 2;
        const float4 v = *reinterpret_cast<const float4*>(smem + S_XRAW + c * 16);
        const __nv_bfloat16 hx = __float2bfloat16(v.x), hy = __float2bfloat16(v.y);
        const __nv_bfloat16 hz = __float2bfloat16(v.z), hw = __float2bfloat16(v.w);
        uint2 hi, lo;
        hi.x = bf2u(__nv_bfloat162(hx, hy));
        hi.y = bf2u(__nv_bfloat162(hz, hw));
        lo.x = bf2u(__floats2bfloat162_rn(v.x - __bfloat162float(hx),
                                          v.y - __bfloat162float(hy)));
        lo.y = bf2u(__floats2bfloat162_rn(v.z - __bfloat162float(hz),
                                          v.w - __bfloat162float(hw)));
        const uint32_t byte = (uint32_t)row * ROW_B + k * 2;
        *reinterpret_cast<uint2*>(smem + XS_HI + byte) = hi;
        *reinterpret_cast<uint2*>(smem + XS_LO + byte) = lo;
    }
    CP_WAIT(0);        // dest landed (this thread's view)
    __syncthreads();   // publish dest + mhl; XRAW reads done -> WS writable

    // ---- 4. W gather: dest from LDS -> means table LDS -> PRMT split ----
    {
        const int tbase = o0 * 16;
#pragma unroll
        for (int j = 0; j < 4; j++) {
            const int s = tid + j * THREADS;      // 0..2047
            const int4 dd = *reinterpret_cast<const int4*>(smem + S_DEST + s * 16);
            const uint32_t m0v = mhl[dd.x - tbase], m1v = mhl[dd.y - tbase];
            const uint32_t m2v = mhl[dd.z - tbase], m3v = mhl[dd.w - tbase];
            const int o  = s >> 5;
            const int kq = s & 31;
            uint2 hi, lo;
            hi.x = __byte_perm(m0v, m1v, 0x5410);
            hi.y = __byte_perm(m2v, m3v, 0x5410);
            lo.x = __byte_perm(m0v, m1v, 0x7632);
            lo.y = __byte_perm(m2v, m3v, 0x7632);
            *reinterpret_cast<uint2*>(smem + WS_HI + o * ROW_B + kq * 8) = hi;
            *reinterpret_cast<uint2*>(smem + WS_LO + o * ROW_B + kq * 8) = lo;
        }
    }
    __syncthreads();

    // ---- 5. mma.sync mainloop: warp = 16 batches x 32 outputs (R12) ----
    const int m0 = (wid & 7) * 16;
    const int nh = wid >> 3;
    float acc[4][4];
#pragma unroll
    for (int n = 0; n < 4; n++)
#pragma unroll
        for (int i = 0; i < 4; i++) acc[n][i] = 0.f;

    const uint32_t a_row  = (uint32_t)(m0 + (lid & 15)) * ROW_B;
    const uint32_t a_coff = (uint32_t)(lid >> 4) * 16;
    const uint32_t b_row  = (uint32_t)(lid & 7) * ROW_B;
    const uint32_t b_coff = (uint32_t)(lid >> 3) * 16;

#pragma unroll
    for (int kp = 0; kp < 4; kp++) {
        uint32_t ah0[4], ah1[4], al0[4], al1[4];
        {
            const uint32_t c0 = (uint32_t)(kp * 64) + a_coff;
            const uint32_t c1 = c0 + 32;
            LDSM_X4(ah0[0], ah0[1], ah0[2], ah0[3], sb + XS_HI + a_row + c0);
            LDSM_X4(ah1[0], ah1[1], ah1[2], ah1[3], sb + XS_HI + a_row + c1);
            LDSM_X4(al0[0], al0[1], al0[2], al0[3], sb + XS_LO + a_row + c0);
            LDSM_X4(al1[0], al1[1], al1[2], al1[3], sb + XS_LO + a_row + c1);
        }
#pragma unroll
        for (int n = 0; n < 4; n++) {
            const uint32_t bbase = (uint32_t)((nh * 4 + n) * 8) * ROW_B
                                 + (uint32_t)(kp * 64) + b_coff;
            uint32_t bh[4], bl[4];
            LDSM_X4(bh[0], bh[1], bh[2], bh[3], sb + WS_HI + b_row + bbase);
            LDSM_X4(bl[0], bl[1], bl[2], bl[3], sb + WS_LO + b_row + bbase);
            MMA_BF16(acc[n], ah0[0], ah0[1], ah0[2], ah0[3], bh[0], bh[1]);
            MMA_BF16(acc[n], al0[0], al0[1], al0[2], al0[3], bh[0], bh[1]);
            MMA_BF16(acc[n], ah0[0], ah0[1], ah0[2], ah0[3], bl[0], bl[1]);
            MMA_BF16(acc[n], ah1[0], ah1[1], ah1[2], ah1[3], bh[2], bh[3]);
            MMA_BF16(acc[n], al1[0], al1[1], al1[2], al1[3], bh[2], bh[3]);
            MMA_BF16(acc[n], ah1[0], ah1[1], ah1[2], ah1[3], bl[2], bl[3]);
        }
    }

    // ---- 6. write partials ----
    {
        const int g  = lid >> 2;
        const int tg = lid & 3;
        float* r0 = g_part + ((size_t)(ks * B_DIM + m0 + g))     * OUT_DIM
                  + o0 + nh * 32 + 2 * tg;
        float* r1 = g_part + ((size_t)(ks * B_DIM + m0 + g + 8)) * OUT_DIM
                  + o0 + nh * 32 + 2 * tg;
#pragma unroll
        for (int n = 0; n < 4; n++) {
            *reinterpret_cast<float2*>(r0 + n * 8) = make_float2(acc[n][0], acc[n][1]);
            *reinterpret_cast<float2*>(r1 + n * 8) = make_float2(acc[n][2], acc[n][3]);
        }
    }

    // ---- 7. per-tile barrier: all 8 CTAs of this oy (monotonic) ----
    __threadfence();
    __syncthreads();
    if (tid == 0) {
        const unsigned v = atomicAdd(&g_done[oy], 1u) + 1u;
        const unsigned target = ((v - 1u) / (unsigned)KSPLIT + 1u) * (unsigned)KSPLIT;
        while (*(volatile unsigned*)&g_done[oy] < target) { }
    }
    __syncthreads();
    __threadfence();

    // ---- 8. distributed reduce: CTA ks owns batches ks*16..+15 ----
    {
        const int b  = ks * 16 + (tid >> 5);
        const int oo = (tid & 31) * 2;
        const float* p = g_part + (size_t)b * OUT_DIM + o0 + oo;
        float2 a = make_float2(0.f, 0.f);
#pragma unroll
        for (int k = 0; k < KSPLIT; k++) {
            const float2 v = *reinterpret_cast<const float2*>(
                p + (size_t)k * (B_DIM * OUT_DIM));
            a.x += v.x; a.y += v.y;
        }
        const float2 bb = *reinterpret_cast<const float2*>(bias + o0 + oo);
        a.x += bb.x; a.y += bb.y;
        *reinterpret_cast<float2*>(out + (size_t)b * OUT_DIM + o0 + oo) = a;
    }
}

extern "C" void kernel_launch(void* const* d_in, const int* in_sizes, int n_in,
                              void* d_out, int out_size)
{
    (void)in_sizes; (void)n_in; (void)out_size;
    const float* x     = (const float*)d_in[0];   // [128,1024] f32
    const float* means = (const float*)d_in[1];   // [1024,16]  f32
    const float* bias  = (const float*)d_in[2];   // [1024]     f32
    // d_in[3] = col_idx (identity layout per row; unused)
    const int*   dest  = (const int*)d_in[4];     // [1024*1024] i32

    cudaFuncSetAttribute(sic_mma, cudaFuncAttributeMaxDynamicSharedMemorySize,
                         SMEM_BYTES);
    sic_mma<<<GRID, THREADS, SMEM_BYTES>>>(x, means, bias, dest, (float*)d_out);
}